// round 12
// baseline (speedup 1.0000x reference)
#include <cuda_runtime.h>
#include <cstdint>

// Problem constants: B=64, R=32, N=16384, D=64, O=8
#define PB 64
#define PR 32
#define PN 16384
#define PD 64
#define PO 8

#define BLOCKS_PER_B 16
#define THREADS 256          // 8 warps
#define WARPS (THREADS / 32)

// Global scratch (zero-initialized at load; the finalizer resets it each run).
__device__ float        g_s[PB][PD];
__device__ float        g_cnt[PB];
__device__ unsigned int g_ticket[PB];

// release fetch-add on the ticket: orders this block's prior RED/atomics
// before the bump.
__device__ __forceinline__ void ticket_release(unsigned int* p) {
    unsigned int old;
    asm volatile("atom.release.gpu.global.add.u32 %0, [%1], 1;"
                 : "=r"(old) : "l"(p) : "memory");
}

__device__ __forceinline__ unsigned int ld_acquire(const unsigned int* p) {
    unsigned int v;
    asm volatile("ld.acquire.gpu.global.u32 %0, [%1];"
                 : "=r"(v) : "l"(p) : "memory");
    return v;
}

// fire-and-forget vector reduction: g_s push in 16 ops instead of 64
__device__ __forceinline__ void red_add_v4(float* p, float4 v) {
    asm volatile("red.global.add.v4.f32 [%0], {%1, %2, %3, %4};"
                 :: "l"(p), "f"(v.x), "f"(v.y), "f"(v.z), "f"(v.w)
                 : "memory");
}

// ---------------------------------------------------------------------------
// Grid (BLOCKS_PER_B, PB), 256 threads. Per warp: 128 rows = one int4 triplet
// per lane (three LDG.128 front-batched; 12.6 MB total = traffic floor).
// Ballot-compacted gather of ~0.74% valid rows, warp L2-normalize, smem
// reduction, red.v4 push to g_s, release ticket.
// Block x=0 is the DESIGNATED FINALIZER: after pushing its own partial it
// loads l_local and computes the s-independent norms WHILE spinning on the
// ticket (overlap), then finishes dot + epilogue and resets the scratch.
// Safe: all 1024 CTAs (32 regs / 264B smem) are co-resident in one wave.
// ---------------------------------------------------------------------------
__global__ __launch_bounds__(THREADS)
void ssfw_fused_kernel(const float* __restrict__ l_local,
                       const float* __restrict__ h_context,
                       const float* __restrict__ lambda_so,
                       const int* __restrict__ center_o,
                       const int* __restrict__ o_types,
                       const int* __restrict__ adj_mask,
                       const int* __restrict__ two_hop_mask,
                       float* __restrict__ out) {
    __shared__ float s[PD];
    __shared__ float scnt;

    const int b    = blockIdx.y;
    const int lane = threadIdx.x & 31;
    const int warp = threadIdx.x >> 5;

    if (threadIdx.x < PD) s[threadIdx.x] = 0.0f;
    if (threadIdx.x == 0) scnt = 0.0f;

    // ---- front-batched mask loads: one int4 triplet per lane ----
    const int rowsPerBlock = PN / BLOCKS_PER_B;            // 1024
    const int rowsPerWarp  = rowsPerBlock / WARPS;         // 128
    const int base         = blockIdx.x * rowsPerBlock + warp * rowsPerWarp;
    const int vec          = (base >> 2) + lane;           // int4 index

    const int4* ot4 = (const int4*)(o_types      + (size_t)b * PN);
    const int4* am4 = (const int4*)(adj_mask     + (size_t)b * PN);
    const int4* th4 = (const int4*)(two_hop_mask + (size_t)b * PN);

    const int4 ot = __ldg(&ot4[vec]);
    const int4 am = __ldg(&am4[vec]);
    const int4 th = __ldg(&th4[vec]);

    const int cb = center_o[b];

    const bool v0 = ((am.x | th.x) != 0) && (ot.x == cb);
    const bool v1 = ((am.y | th.y) != 0) && (ot.y == cb);
    const bool v2 = ((am.z | th.z) != 0) && (ot.z == cb);
    const bool v3 = ((am.w | th.w) != 0) && (ot.w == cb);

    float accx = 0.0f, accy = 0.0f;
    int   cntw = 0;

    __syncthreads();   // smem zero-init visible

    const float* ctxBase = h_context + (size_t)b * PN * PD;

    // ---- gather: ballot-compacted, warp-cooperative row normalize ----
    #pragma unroll
    for (int t = 0; t < 4; ++t) {
        const bool vt = (t == 0) ? v0 : (t == 1) ? v1 : (t == 2) ? v2 : v3;
        unsigned m = __ballot_sync(0xffffffffu, vt);
        cntw += __popc(m);
        while (m) {
            const int j = __ffs(m) - 1;
            m &= (m - 1);
            const int row = base + 4 * j + t;
            const float2 v = ((const float2*)(ctxBase + (size_t)row * PD))[lane];
            float ss = v.x * v.x + v.y * v.y;
            #pragma unroll
            for (int o = 16; o; o >>= 1)
                ss += __shfl_xor_sync(0xffffffffu, ss, o);
            const float inv = rsqrtf(fmaxf(ss, 1e-12f));
            accx += v.x * inv;
            accy += v.y * inv;
        }
    }

    // block-local reduction into smem
    if (accx != 0.0f || accy != 0.0f) {
        atomicAdd(&s[2 * lane],     accx);
        atomicAdd(&s[2 * lane + 1], accy);
    }
    if (lane == 0 && cntw) atomicAdd(&scnt, (float)cntw);
    __syncthreads();

    // warp 0 pushes the block partial (16 red.v4) and releases the ticket
    if (warp == 0) {
        if (lane < 16) {
            const float4 sv = ((const float4*)s)[lane];
            red_add_v4(&g_s[b][4 * lane], sv);
        }
        if (lane == 0) {
            atomicAdd(&g_cnt[b], scnt);
            ticket_release(&g_ticket[b]);
        }
    }

    if (blockIdx.x != 0) return;

    // =======================================================================
    // Designated finalizer (block x == 0)
    // =======================================================================

    // ---- overlap: load l_local + compute s-independent norms while the
    //      other 15 blocks finish ----
    float2 lv[PR / WARPS];
    float  linv[PR / WARPS];
    #pragma unroll
    for (int rr = 0; rr < PR / WARPS; ++rr) {
        const int r = warp + rr * WARPS;
        lv[rr] = ((const float2*)(l_local + ((size_t)b * PR + r) * PD))[lane];
    }
    #pragma unroll
    for (int rr = 0; rr < PR / WARPS; ++rr) {
        float ss = lv[rr].x * lv[rr].x + lv[rr].y * lv[rr].y;
        #pragma unroll
        for (int o = 16; o; o >>= 1)
            ss += __shfl_xor_sync(0xffffffffu, ss, o);
        linv[rr] = rsqrtf(fmaxf(ss, 1e-12f));
    }

    // ---- wait for all 16 tickets (acquire) ----
    if (threadIdx.x == 0) {
        while (ld_acquire(&g_ticket[b]) < BLOCKS_PER_B) __nanosleep(20);
    }
    __syncthreads();

    // ---- finish: dot against the complete g_s + epilogue ----
    const float cntf  = g_cnt[b];
    const float invc9 = 1.0f / fmaxf(cntf, 1e-9f);
    const float invc1 = 1.0f / fmaxf(cntf, 1.0f);

    const float sx = g_s[b][2 * lane];
    const float sy = g_s[b][2 * lane + 1];

    #pragma unroll
    for (int rr = 0; rr < PR / WARPS; ++rr) {          // 4 rows per warp
        const int r = warp + rr * WARPS;
        float dot = lv[rr].x * sx + lv[rr].y * sy;
        #pragma unroll
        for (int o = 16; o; o >>= 1)
            dot += __shfl_xor_sync(0xffffffffu, dot, o);
        if (lane == 0) {
            const float avg = dot * linv[rr] * invc9;
            const float lam = lambda_so[r * PO + cb];
            out[b * PR + r] = fmaxf(lam * invc1, 0.0f) * (1.0f - avg);
        }
    }

    // ---- reset scratch for the next (graph-replayed) run ----
    __syncthreads();
    if (threadIdx.x < PD) g_s[b][threadIdx.x] = 0.0f;
    if (threadIdx.x == 0) { g_cnt[b] = 0.0f; g_ticket[b] = 0u; }
}

// ---------------------------------------------------------------------------
// Launch. Input order: l_local, h_context, lambda_so, center_o, o_types,
//                      adj_mask, two_hop_mask
// ---------------------------------------------------------------------------
extern "C" void kernel_launch(void* const* d_in, const int* in_sizes, int n_in,
                              void* d_out, int out_size) {
    const float* l_local   = (const float*)d_in[0];
    const float* h_context = (const float*)d_in[1];
    const float* lambda_so = (const float*)d_in[2];
    const int*   center_o  = (const int*)d_in[3];
    const int*   o_types   = (const int*)d_in[4];
    const int*   adj_mask  = (const int*)d_in[5];
    const int*   two_hop   = (const int*)d_in[6];
    float*       out       = (float*)d_out;

    dim3 grid(BLOCKS_PER_B, PB);
    ssfw_fused_kernel<<<grid, THREADS>>>(l_local, h_context, lambda_so,
                                         center_o, o_types, adj_mask, two_hop,
                                         out);
}

// round 15
// speedup vs baseline: 1.0213x; 1.0213x over previous
#include <cuda_runtime.h>
#include <cstdint>

// Problem constants: B=64, R=32, N=16384, D=64, O=8
#define PB 64
#define PR 32
#define PN 16384
#define PD 64
#define PO 8

#define BLOCKS_PER_B 16
#define THREADS 256          // 8 warps
#define WARPS (THREADS / 32)

// Global scratch (zero-initialized at load; the finalizing block resets it
// each run -> graph-replay-deterministic).
__device__ float        g_s[PB][PD];
__device__ float        g_cnt[PB];
__device__ unsigned int g_ticket[PB];

// acq_rel fetch-add on the ticket: release orders this block's prior global
// atomics before the bump; acquire on the returned value orders the
// finalizer's subsequent reads. Replaces two __threadfence() calls.
__device__ __forceinline__ unsigned int ticket_acq_rel(unsigned int* p) {
    unsigned int old;
    asm volatile("atom.acq_rel.gpu.global.add.u32 %0, [%1], 1;"
                 : "=r"(old) : "l"(p) : "memory");
    return old;
}

// ---------------------------------------------------------------------------
// Grid (BLOCKS_PER_B, PB), 256 threads. Each warp covers exactly 128 rows:
// one int4 (LDG.128) per lane from each of the 3 mask streams, all issued
// back-to-back (max MLP). Ballot-compacted gather of the ~0.74% valid
// h_context rows, warp L2-normalize, smem reduction, global atomics.
// Last block per b (acq_rel ticket) finalizes 32 outputs and resets scratch.
// ---------------------------------------------------------------------------
__global__ __launch_bounds__(THREADS)
void ssfw_fused_kernel(const float* __restrict__ l_local,
                       const float* __restrict__ h_context,
                       const float* __restrict__ lambda_so,
                       const int* __restrict__ center_o,
                       const int* __restrict__ o_types,
                       const int* __restrict__ adj_mask,
                       const int* __restrict__ two_hop_mask,
                       float* __restrict__ out) {
    __shared__ float s[PD];
    __shared__ float scnt;
    __shared__ int   sIsLast;

    const int b    = blockIdx.y;
    const int lane = threadIdx.x & 31;
    const int warp = threadIdx.x >> 5;

    if (threadIdx.x < PD) s[threadIdx.x] = 0.0f;
    if (threadIdx.x == 0) scnt = 0.0f;

    const int cb = center_o[b];

    // ---- Phase 1: masked scan, one int4 triplet per lane ----
    const int rowsPerBlock = PN / BLOCKS_PER_B;            // 1024
    const int rowsPerWarp  = rowsPerBlock / WARPS;         // 128
    const int base         = blockIdx.x * rowsPerBlock + warp * rowsPerWarp;
    const int vec          = (base >> 2) + lane;           // int4 index

    const int4* ot4 = (const int4*)(o_types      + (size_t)b * PN);
    const int4* am4 = (const int4*)(adj_mask     + (size_t)b * PN);
    const int4* th4 = (const int4*)(two_hop_mask + (size_t)b * PN);

    // three independent LDG.128 issued back-to-back
    const int4 ot = __ldg(&ot4[vec]);
    const int4 am = __ldg(&am4[vec]);
    const int4 th = __ldg(&th4[vec]);

    const bool v0 = ((am.x | th.x) != 0) && (ot.x == cb);
    const bool v1 = ((am.y | th.y) != 0) && (ot.y == cb);
    const bool v2 = ((am.z | th.z) != 0) && (ot.z == cb);
    const bool v3 = ((am.w | th.w) != 0) && (ot.w == cb);

    float accx = 0.0f, accy = 0.0f;
    int   cntw = 0;

    __syncthreads();   // smem zero-init visible

    const float* ctxBase = h_context + (size_t)b * PN * PD;

    #pragma unroll
    for (int t = 0; t < 4; ++t) {
        const bool vt = (t == 0) ? v0 : (t == 1) ? v1 : (t == 2) ? v2 : v3;
        unsigned m = __ballot_sync(0xffffffffu, vt);
        cntw += __popc(m);
        while (m) {
            const int j = __ffs(m) - 1;
            m &= (m - 1);
            const int row = base + 4 * j + t;
            // warp cooperatively loads this 256B row: lane -> float2 slice
            const float2 v = ((const float2*)(ctxBase + (size_t)row * PD))[lane];
            float ss = v.x * v.x + v.y * v.y;
            #pragma unroll
            for (int o = 16; o; o >>= 1)
                ss += __shfl_xor_sync(0xffffffffu, ss, o);
            const float inv = rsqrtf(fmaxf(ss, 1e-12f));
            accx += v.x * inv;
            accy += v.y * inv;
        }
    }

    // block-local reduction into smem
    atomicAdd(&s[2 * lane],     accx);
    atomicAdd(&s[2 * lane + 1], accy);
    if (lane == 0) atomicAdd(&scnt, (float)cntw);
    __syncthreads();

    // warp 0 pushes the block partial to global scratch; thread 0 then bumps
    // the ticket with acq_rel (orders the pushes without __threadfence).
    if (warp == 0) {
        atomicAdd(&g_s[b][2 * lane],     s[2 * lane]);
        atomicAdd(&g_s[b][2 * lane + 1], s[2 * lane + 1]);
        if (lane == 0) {
            atomicAdd(&g_cnt[b], scnt);
            const unsigned old = ticket_acq_rel(&g_ticket[b]);
            sIsLast = (old == BLOCKS_PER_B - 1);
        }
    }
    __syncthreads();
    if (!sIsLast) return;

    // ---- Phase 2 (last block per b): finalize 32 outputs ----
    const float cntf  = g_cnt[b];
    const float invc9 = 1.0f / fmaxf(cntf, 1e-9f);
    const float invc1 = 1.0f / fmaxf(cntf, 1.0f);

    const float sx = g_s[b][2 * lane];
    const float sy = g_s[b][2 * lane + 1];

    #pragma unroll
    for (int rr = 0; rr < PR / WARPS; ++rr) {          // 4 rows per warp
        const int r = warp + rr * WARPS;
        const float2 v =
            ((const float2*)(l_local + ((size_t)b * PR + r) * PD))[lane];
        float ss  = v.x * v.x + v.y * v.y;
        float dot = v.x * sx + v.y * sy;
        #pragma unroll
        for (int o = 16; o; o >>= 1) {
            ss  += __shfl_xor_sync(0xffffffffu, ss,  o);
            dot += __shfl_xor_sync(0xffffffffu, dot, o);
        }
        if (lane == 0) {
            const float inv = rsqrtf(fmaxf(ss, 1e-12f));
            const float avg = dot * inv * invc9;
            const float lam = lambda_so[r * PO + cb];
            out[b * PR + r] = fmaxf(lam * invc1, 0.0f) * (1.0f - avg);
        }
    }

    // ---- reset scratch for the next (graph-replayed) run ----
    __syncthreads();
    if (threadIdx.x < PD) g_s[b][threadIdx.x] = 0.0f;
    if (threadIdx.x == 0) { g_cnt[b] = 0.0f; g_ticket[b] = 0u; }
}

// ---------------------------------------------------------------------------
// Launch. Input order: l_local, h_context, lambda_so, center_o, o_types,
//                      adj_mask, two_hop_mask
// ---------------------------------------------------------------------------
extern "C" void kernel_launch(void* const* d_in, const int* in_sizes, int n_in,
                              void* d_out, int out_size) {
    const float* l_local   = (const float*)d_in[0];
    const float* h_context = (const float*)d_in[1];
    const float* lambda_so = (const float*)d_in[2];
    const int*   center_o  = (const int*)d_in[3];
    const int*   o_types   = (const int*)d_in[4];
    const int*   adj_mask  = (const int*)d_in[5];
    const int*   two_hop   = (const int*)d_in[6];
    float*       out       = (float*)d_out;

    dim3 grid(BLOCKS_PER_B, PB);
    ssfw_fused_kernel<<<grid, THREADS>>>(l_local, h_context, lambda_so,
                                         center_o, o_types, adj_mask, two_hop,
                                         out);
}